// round 14
// baseline (speedup 1.0000x reference)
#include <cuda_runtime.h>
#include <cuda_bf16.h>
#include <math.h>

#define NREV 4096
#define LTOK 128
#define DW   200
#define AASP 32
#define NNEG 5
#define BUSR 1024

// ---------------- scratch (device globals) -----------------------------------
__device__ __align__(16) float g_q[NREV * DW];
__device__ __align__(16) float g_rs[NREV * DW];
__device__ __align__(16) float g_hinge[NREV];
__device__ __align__(16) float g_sq[BUSR];
__device__ float g_U[1];
__device__ __align__(16) __nv_bfloat16 g_Wwb[AASP * DW];
__device__ __align__(16) __nv_bfloat16 g_Twb[DW * AASP];
__device__ int g_ubnd[BUSR + 1];
__device__ int g_ibnd[BUSR + 1];
__device__ unsigned int g_cnt;

__device__ __forceinline__ float dot4(float4 a, float4 b) {
    return a.x * b.x + a.y * b.y + a.z * b.z + a.w * b.w;
}
__device__ __forceinline__ float warp_sum(float v) {
    #pragma unroll
    for (int o = 16; o; o >>= 1) v += __shfl_down_sync(0xffffffffu, v, o);
    return v;
}
__device__ __forceinline__ uint2 pack_bf16x4(float4 v) {
    __nv_bfloat162 a = __float22bfloat162_rn(make_float2(v.x, v.y));
    __nv_bfloat162 b = __float22bfloat162_rn(make_float2(v.z, v.w));
    uint2 u;
    u.x = *(unsigned int*)&a;
    u.y = *(unsigned int*)&b;
    return u;
}
__device__ __forceinline__ float2 bf2f(unsigned int u) {
    return __bfloat1622float2(*(__nv_bfloat162*)&u);
}
// ---- f32x2 packed math (sm_103a) ----
__device__ __forceinline__ unsigned long long pk2(float x, float y) {
    unsigned long long r;
    asm("mov.b64 %0, {%1, %2};" : "=l"(r) : "f"(x), "f"(y));
    return r;
}
__device__ __forceinline__ float2 upk2(unsigned long long v) {
    float2 f;
    asm("mov.b64 {%0, %1}, %2;" : "=f"(f.x), "=f"(f.y) : "l"(v));
    return f;
}
__device__ __forceinline__ unsigned long long fma2(unsigned long long a,
                                                   unsigned long long b,
                                                   unsigned long long c) {
    unsigned long long d;
    asm("fma.rn.f32x2 %0, %1, %2, %3;" : "=l"(d) : "l"(a), "l"(b), "l"(c));
    return d;
}

#define QK_BLOCKS (NREV / 32)   // 128 CTAs, 32 reviews each

// ---------------- K1: q = rev_pos @ M_w  (+ fused prep blocks) ----------------
// 256 threads (8 warps). Warp w: reviews (w&3)*8..+7, output half h = w>>2.
// 8 reviews/warp => 16 fma2 per m-load (latency hidden by issue). M_w via L1.
__global__ __launch_bounds__(256, 2)
void qk(const float* __restrict__ rp, const float* __restrict__ Mw,
        const float* __restrict__ Ww, const float* __restrict__ Tw,
        const int* __restrict__ usi, const int* __restrict__ isi, int F) {
    int tid = threadIdx.x, w = tid >> 5, lane = tid & 31;

    // -------- prep blocks: bf16 weights + segment boundaries --------
    if (blockIdx.x >= QK_BLOCKS) {
        int i = (blockIdx.x - QK_BLOCKS) * 256 + tid;
        if (i < AASP * DW) {
            g_Wwb[i] = __float2bfloat16(Ww[i]);
            g_Twb[i] = __float2bfloat16(Tw[i]);
        }
        if (i < F) {
            int u = usi[i];
            if (i == 0 || usi[i - 1] != u) g_ubnd[u] = i;
            int v = isi[i];
            if (i == 0 || isi[i - 1] != v) g_ibnd[v] = i;
        }
        if (i == 0) { g_ubnd[BUSR] = F; g_ibnd[BUSR] = F; }
        return;
    }

    __shared__ float rps[32 * DW];   // 25.6 KB
    {
        int n0 = blockIdx.x * 32;
        const float4* rp4 = (const float4*)(rp + n0 * DW);
        float4* rps4w = (float4*)rps;
        for (int i = tid; i < 32 * DW / 4; i += 256) rps4w[i] = __ldg(&rp4[i]);
    }
    __syncthreads();

    int g = w & 3;           // review group: 8 reviews
    int h = w >> 2;          // output-chunk half
    bool act = (h == 0) || (lane < 18);
    int c = h ? (32 + (lane < 18 ? lane : 0)) : lane;

    const float4* Mw4  = (const float4*)Mw;
    const float4* rps4 = (const float4*)rps;

    unsigned long long acc[8][2];
    #pragma unroll
    for (int j = 0; j < 8; j++) { acc[j][0] = 0ull; acc[j][1] = 0ull; }

    for (int d2b = 0; d2b < 50; d2b++) {
        float4 m4[4];
        #pragma unroll
        for (int s = 0; s < 4; s++)                     // 4 LDG in flight
            m4[s] = __ldg(&Mw4[(d2b * 4 + s) * 50 + c]);
        float4 r4[8];
        #pragma unroll
        for (int j = 0; j < 8; j++) r4[j] = rps4[(g * 8 + j) * 50 + d2b];  // broadcast
        #pragma unroll
        for (int s = 0; s < 4; s++) {
            unsigned long long m01 = pk2(m4[s].x, m4[s].y), m23 = pk2(m4[s].z, m4[s].w);
            #pragma unroll
            for (int j = 0; j < 8; j++) {
                float r = (s == 0) ? r4[j].x : (s == 1) ? r4[j].y
                        : (s == 2) ? r4[j].z : r4[j].w;
                unsigned long long rr = pk2(r, r);
                acc[j][0] = fma2(rr, m01, acc[j][0]);
                acc[j][1] = fma2(rr, m23, acc[j][1]);
            }
        }
    }

    if (act) {
        int n0 = blockIdx.x * 32;
        float4* gq4 = (float4*)g_q;
        #pragma unroll
        for (int j = 0; j < 8; j++) {
            float2 a0 = upk2(acc[j][0]), a1 = upk2(acc[j][1]);
            float4 o; o.x = a0.x; o.y = a0.y; o.z = a1.x; o.w = a1.y;
            gq4[(n0 + g * 8 + j) * 50 + c] = o;
        }
    }
}

// ---------------- K2: fused per-review ABAE, bf16 SMEM tile, occ 4 ------------
#define SM_WORDS 13608

__global__ __launch_bounds__(256, 4)
void mainkern(const int* __restrict__ hist, const float* __restrict__ wemb,
              const float* __restrict__ rneg, const float* __restrict__ Wb,
              const float* __restrict__ Tw) {
    extern __shared__ float sm[];
    int n = blockIdx.x;
    int tid = threadIdx.x, w = tid >> 5, lane = tid & 31;

    // -------- extra block: U_loss (exact fp32 Tw) --------
    if (n == NREV) {
        float* Ts  = sm;          // 6400
        float* nrm = sm + 6400;   // 32
        float* red = sm + 6432;   // 8
        for (int i = tid; i < DW * AASP; i += 256) Ts[i] = Tw[i];
        __syncthreads();
        if (tid < AASP) {
            float s = 0.f;
            for (int d = 0; d < DW; d++) { float v = Ts[d * AASP + tid]; s += v * v; }
            nrm[tid] = fmaxf(sqrtf(s), 1e-12f);
        }
        __syncthreads();
        float part = 0.f;
        for (int pr = tid; pr < AASP * AASP; pr += 256) {
            int a = pr >> 5, b = pr & 31;
            float s = 0.f;
            for (int d = 0; d < DW; d++) s += Ts[d * AASP + a] * Ts[d * AASP + b];
            float g = s / (nrm[a] * nrm[b]);
            float diff = g - ((a == b) ? 1.f : 0.f);
            part += diff * diff;
        }
        float v = warp_sum(part);
        if (lane == 0) red[w] = v;
        __syncthreads();
        if (tid == 0) {
            float t = 0.f;
            for (int k = 0; k < 8; k++) t += red[k];
            g_U[0] = t / (float)(AASP * AASP);
        }
        return;
    }

    uint2* eb2  = (uint2*)sm;
    float* qs   = sm + 12800;
    float* ax   = sm + 13000;
    float* zs   = sm + 13128;
    float* p    = sm + 13328;
    float* part = sm + 13360;
    float* tot  = sm + 13464;
    int*   tok  = (int*)(sm + 13480);

    if (tid < LTOK) tok[tid] = hist[n * LTOK + tid];
    if (tid < DW)   qs[tid]  = g_q[n * DW + tid];
    __syncthreads();

    bool hi = (lane < 18);
    const float4* qs4 = (const float4*)qs;
    float4 qv0 = qs4[lane];
    float4 qv1 = hi ? qs4[32 + lane] : make_float4(0, 0, 0, 0);
    const float4* we4 = (const float4*)wemb;

    // -------- single gather + dx (fp32 exact) + bf16 tile store --------
    #pragma unroll
    for (int t0 = 0; t0 < 16; t0 += 4) {
        float4 v0[4], v1[4];
        #pragma unroll
        for (int t = 0; t < 4; t++) {
            int rb = tok[w * 16 + t0 + t] * 50;
            v0[t] = __ldg(&we4[rb + lane]);
            v1[t] = hi ? __ldg(&we4[rb + 32 + lane]) : make_float4(0, 0, 0, 0);
        }
        float a[4];
        #pragma unroll
        for (int t = 0; t < 4; t++) {
            int l = w * 16 + t0 + t;
            eb2[l * 50 + lane] = pack_bf16x4(v0[t]);
            if (hi) eb2[l * 50 + 32 + lane] = pack_bf16x4(v1[t]);
            a[t] = dot4(v0[t], qv0) + dot4(v1[t], qv1);
        }
        #pragma unroll
        for (int t = 0; t < 4; t++) a[t] = warp_sum(a[t]);
        if (lane == 0) {
            #pragma unroll
            for (int t = 0; t < 4; t++) ax[w * 16 + t0 + t] = a[t];
        }
    }
    __syncthreads();

    // -------- softmax over 128 tokens (warp 0) --------
    if (w == 0) {
        float v0 = ax[lane], v1 = ax[lane + 32], v2 = ax[lane + 64], v3 = ax[lane + 96];
        float m = fmaxf(fmaxf(v0, v1), fmaxf(v2, v3));
        #pragma unroll
        for (int o = 16; o; o >>= 1) m = fmaxf(m, __shfl_xor_sync(0xffffffffu, m, o));
        v0 = __expf(v0 - m); v1 = __expf(v1 - m);
        v2 = __expf(v2 - m); v3 = __expf(v3 - m);
        float s = (v0 + v1) + (v2 + v3);
        #pragma unroll
        for (int o = 16; o; o >>= 1) s += __shfl_xor_sync(0xffffffffu, s, o);
        float inv = 1.f / s;
        ax[lane] = v0 * inv; ax[lane + 32] = v1 * inv;
        ax[lane + 64] = v2 * inv; ax[lane + 96] = v3 * inv;
    }
    __syncthreads();

    // -------- z_s from bf16 SMEM tile (reshape trick, flat slices) --------
    {
        const float4* ax4 = (const float4*)ax;
        float4 av = ax4[lane];
        #pragma unroll
        for (int j0 = 0; j0 < 24; j0 += 4) {
            float a[4];
            #pragma unroll
            for (int k = 0; k < 4; k++) {
                int d = w + 8 * (j0 + k);
                uint2 u = eb2[d * 32 + lane];
                float2 f0 = bf2f(u.x), f1 = bf2f(u.y);
                a[k] = f0.x * av.x + f0.y * av.y + f1.x * av.z + f1.y * av.w;
            }
            #pragma unroll
            for (int k = 0; k < 4; k++) a[k] = warp_sum(a[k]);
            if (lane == 0) {
                #pragma unroll
                for (int k = 0; k < 4; k++) zs[w + 8 * (j0 + k)] = a[k];
            }
        }
        {   // leftover d = 192 + w
            int d = 192 + w;
            uint2 u = eb2[d * 32 + lane];
            float2 f0 = bf2f(u.x), f1 = bf2f(u.y);
            float a = warp_sum(f0.x * av.x + f0.y * av.y + f1.x * av.z + f1.y * av.w);
            if (lane == 0) zs[d] = a;
        }
    }
    __syncthreads();

    // -------- prefetch negatives (consumed in final phase) --------
    float ng[NNEG];
    #pragma unroll
    for (int k = 0; k < NNEG; k++)
        ng[k] = (tid < DW) ? __ldg(&rneg[(n * NNEG + k) * DW + tid]) : 0.f;

    // -------- logits = z_s @ W_w^T + W_b (bf16 weights) --------
    {
        const float4* zs4 = (const float4*)zs;
        float4 zv0 = zs4[lane];
        float4 zv1 = hi ? zs4[32 + lane] : make_float4(0, 0, 0, 0);
        const uint2* wb2 = (const uint2*)g_Wwb;
        #pragma unroll
        for (int j = 0; j < 4; j++) {
            int a = w + 8 * j;
            uint2 u0 = __ldg(&wb2[a * 50 + lane]);
            float2 w0 = bf2f(u0.x), w1 = bf2f(u0.y);
            float acc = w0.x * zv0.x + w0.y * zv0.y + w1.x * zv0.z + w1.y * zv0.w;
            if (hi) {
                uint2 u1 = __ldg(&wb2[a * 50 + 32 + lane]);
                float2 w2 = bf2f(u1.x), w3 = bf2f(u1.y);
                acc += w2.x * zv1.x + w2.y * zv1.y + w3.x * zv1.z + w3.y * zv1.w;
            }
            acc = warp_sum(acc);
            if (lane == 0) p[a] = acc + Wb[a];
        }
    }
    __syncthreads();

    // -------- softmax over A=32 (warp 0) --------
    if (w == 0) {
        float v = p[lane];
        float m = v;
        #pragma unroll
        for (int o = 16; o; o >>= 1) m = fmaxf(m, __shfl_xor_sync(0xffffffffu, m, o));
        float ex = __expf(v - m);
        float s = ex;
        #pragma unroll
        for (int o = 16; o; o >>= 1) s += __shfl_xor_sync(0xffffffffu, s, o);
        p[lane] = ex / s;
    }
    __syncthreads();

    // -------- r_s = p @ T_w^T (bf16 Tw row) ; 13 fused dots --------
    float rsv = 0.f, zsv = 0.f;
    if (tid < DW) {
        const uint4* tb4 = (const uint4*)(g_Twb + tid * AASP);
        float acc = 0.f;
        #pragma unroll
        for (int j = 0; j < 4; j++) {
            uint4 t = __ldg(&tb4[j]);
            float2 a0 = bf2f(t.x), a1 = bf2f(t.y), a2 = bf2f(t.z), a3 = bf2f(t.w);
            acc += a0.x * p[j * 8 + 0] + a0.y * p[j * 8 + 1]
                 + a1.x * p[j * 8 + 2] + a1.y * p[j * 8 + 3]
                 + a2.x * p[j * 8 + 4] + a2.y * p[j * 8 + 5]
                 + a3.x * p[j * 8 + 6] + a3.y * p[j * 8 + 7];
        }
        g_rs[n * DW + tid] = acc;
        rsv = acc;
        zsv = zs[tid];
    }

    float v[13];
    v[0] = zsv * zsv; v[1] = rsv * rsv; v[2] = zsv * rsv;
    #pragma unroll
    for (int k = 0; k < NNEG; k++) { v[3 + k] = ng[k] * ng[k]; v[8 + k] = ng[k] * rsv; }
    #pragma unroll
    for (int x = 0; x < 13; x++) v[x] = warp_sum(v[x]);
    if (lane == 0) {
        #pragma unroll
        for (int x = 0; x < 13; x++) part[w * 13 + x] = v[x];
    }
    __syncthreads();
    if (w == 0 && lane < 13) {
        float s = 0.f;
        #pragma unroll
        for (int k = 0; k < 8; k++) s += part[k * 13 + lane];
        tot[lane] = s;
    }
    __syncthreads();
    if (tid == 0) {
        float nz = fmaxf(sqrtf(tot[0]), 1e-12f);
        float nr = fmaxf(sqrtf(tot[1]), 1e-12f);
        float c1 = tot[2] / (nz * nr);
        float h = 0.f;
        #pragma unroll
        for (int k = 0; k < NNEG; k++) {
            float c2 = tot[8 + k] / (fmaxf(sqrtf(tot[3 + k]), 1e-12f) * nr);
            h += fmaxf(0.f, c2 - c1);
        }
        g_hinge[n] = h;
    }
}

// ---------------- K3: segment means + prediction + final reduce ---------------
__global__ __launch_bounds__(256, 8)
void segpred(const int* __restrict__ uhi, const int* __restrict__ ihi,
             const float* __restrict__ label, float* __restrict__ out) {
    int b = blockIdx.x;
    int tid = threadIdx.x, w = tid >> 5, lane = tid & 31;
    __shared__ int sidx[96];      // [0:48) u, [48:96) i
    __shared__ int meta[4];       // cu, ci, lou, loi
    __shared__ float red[8];
    __shared__ unsigned int rank;

    if (w < 2) {
        const int* bnd = w ? g_ibnd : g_ubnd;
        const int* idx = w ? ihi : uhi;
        int lo = bnd[b], hi2 = bnd[b + 1];
        int cnt = hi2 - lo;
        if (lane == 0) { meta[w] = cnt; meta[2 + w] = lo; }
        for (int j = lane; j < cnt && j < 48; j += 32)
            sidx[w * 48 + j] = idx[lo + j];
    }
    __syncthreads();

    int cu = meta[0], ci = meta[1];
    float prod = 0.f;
    int d = tid;
    if (d < DW) {
        float u0 = 0.f, u1 = 0.f, u2 = 0.f, u3 = 0.f;
        float i0 = 0.f, i1 = 0.f, i2 = 0.f, i3 = 0.f;
        int cuc = cu < 48 ? cu : 48;
        int cic = ci < 48 ? ci : 48;
        int c = cuc < cic ? cuc : cic;
        int j = 0;
        for (; j + 4 <= c; j += 4) {
            u0 += g_rs[sidx[j]      * DW + d];
            i0 += g_rs[sidx[48 + j] * DW + d];
            u1 += g_rs[sidx[j + 1]      * DW + d];
            i1 += g_rs[sidx[48 + j + 1] * DW + d];
            u2 += g_rs[sidx[j + 2]      * DW + d];
            i2 += g_rs[sidx[48 + j + 2] * DW + d];
            u3 += g_rs[sidx[j + 3]      * DW + d];
            i3 += g_rs[sidx[48 + j + 3] * DW + d];
        }
        for (int k = j; k < cuc; k++) u0 += g_rs[sidx[k] * DW + d];
        for (int k = j; k < cic; k++) i0 += g_rs[sidx[48 + k] * DW + d];
        for (int k = 48; k < cu; k++) u0 += g_rs[uhi[meta[2] + k] * DW + d];
        for (int k = 48; k < ci; k++) i0 += g_rs[ihi[meta[3] + k] * DW + d];
        float um = ((u0 + u1) + (u2 + u3)) / (float)cu;
        float im = ((i0 + i1) + (i2 + i3)) / (float)ci;
        prod = um * im;
    }
    float s = warp_sum(prod);
    if (lane == 0) red[w] = s;
    __syncthreads();
    if (tid == 0) {
        float t = 0.f;
        #pragma unroll
        for (int k = 0; k < 8; k++) t += red[k];
        float e = t + 3.5f - label[b];
        g_sq[b] = e * e;
        __threadfence();
        rank = atomicAdd(&g_cnt, 1u);
    }
    __syncthreads();

    // -------- last block: final reductions --------
    if (rank == BUSR - 1) {
        __threadfence();
        const float4* h4 = (const float4*)g_hinge;
        float hsum = 0.f;
        #pragma unroll
        for (int r = 0; r < 4; r++) {
            float4 hv = h4[tid + 256 * r];
            hsum += (hv.x + hv.y) + (hv.z + hv.w);
        }
        hsum = warp_sum(hsum);
        if (lane == 0) red[w] = hsum;
        __syncthreads();
        float hs = 0.f;
        if (tid == 0) {
            #pragma unroll
            for (int k = 0; k < 8; k++) hs += red[k];
        }
        __syncthreads();

        float4 qv = ((const float4*)g_sq)[tid];
        float q = (qv.x + qv.y) + (qv.z + qv.w);
        q = warp_sum(q);
        if (lane == 0) red[w] = q;
        __syncthreads();
        if (tid == 0) {
            float rsum = 0.f;
            #pragma unroll
            for (int k = 0; k < 8; k++) rsum += red[k];
            float rating = rsum / (float)BUSR;
            float J = hs / (float)(NREV * NNEG);
            float abae = g_U[0] + J;
            out[0] = rating + abae;
            out[1] = rating;
            out[2] = abae;
            g_cnt = 0u;
        }
    }
}

// ---------------- launch ------------------------------------------------------
extern "C" void kernel_launch(void* const* d_in, const int* in_sizes, int n_in,
                              void* d_out, int out_size) {
    const int*   hist  = (const int*)d_in[0];
    const float* rpos  = (const float*)d_in[1];
    const float* rneg  = (const float*)d_in[2];
    const float* label = (const float*)d_in[5];
    const int*   uhi   = (const int*)d_in[6];
    const int*   usi   = (const int*)d_in[7];
    const int*   ihi   = (const int*)d_in[8];
    const int*   isi   = (const int*)d_in[9];
    const float* wemb  = (const float*)d_in[10];
    const float* Mw    = (const float*)d_in[11];
    const float* Ww    = (const float*)d_in[12];
    const float* Wb    = (const float*)d_in[13];
    const float* Tw    = (const float*)d_in[14];
    float* out = (float*)d_out;
    int F = in_sizes[6];

    const int SMEM_MAIN = SM_WORDS * 4;              // 54432 B
    cudaFuncSetAttribute(mainkern, cudaFuncAttributeMaxDynamicSharedMemorySize, SMEM_MAIN);

    int prep_elems = (AASP * DW > F) ? AASP * DW : F;
    int prep_blocks = (prep_elems + 255) / 256;
    qk<<<QK_BLOCKS + prep_blocks, 256>>>(rpos, Mw, Ww, Tw, usi, isi, F);
    mainkern<<<NREV + 1, 256, SMEM_MAIN>>>(hist, wemb, rneg, Wb, Tw);
    segpred<<<BUSR, 256>>>(uhi, ihi, label, out);
}

// round 15
// speedup vs baseline: 1.0002x; 1.0002x over previous
#include <cuda_runtime.h>
#include <cuda_bf16.h>
#include <math.h>

#define NREV 4096
#define LTOK 128
#define DW   200
#define AASP 32
#define NNEG 5
#define BUSR 1024

// ---------------- scratch (device globals) -----------------------------------
__device__ __align__(16) float g_q[NREV * DW];
__device__ __align__(16) float g_rs[NREV * DW];
__device__ __align__(16) float g_hinge[NREV];
__device__ __align__(16) float g_sq[BUSR];
__device__ float g_U[1];
__device__ __align__(16) __nv_bfloat16 g_Wwb[AASP * DW];
__device__ __align__(16) __nv_bfloat16 g_Twb[DW * AASP];
__device__ int g_ubnd[BUSR + 1];
__device__ int g_ibnd[BUSR + 1];
__device__ unsigned int g_cnt;

__device__ __forceinline__ float dot4(float4 a, float4 b) {
    return a.x * b.x + a.y * b.y + a.z * b.z + a.w * b.w;
}
__device__ __forceinline__ float warp_sum(float v) {
    #pragma unroll
    for (int o = 16; o; o >>= 1) v += __shfl_down_sync(0xffffffffu, v, o);
    return v;
}
__device__ __forceinline__ uint2 pack_bf16x4(float4 v) {
    __nv_bfloat162 a = __float22bfloat162_rn(make_float2(v.x, v.y));
    __nv_bfloat162 b = __float22bfloat162_rn(make_float2(v.z, v.w));
    uint2 u;
    u.x = *(unsigned int*)&a;
    u.y = *(unsigned int*)&b;
    return u;
}
__device__ __forceinline__ float2 bf2f(unsigned int u) {
    return __bfloat1622float2(*(__nv_bfloat162*)&u);
}
// ---- f32x2 packed math (sm_103a) ----
__device__ __forceinline__ unsigned long long pk2(float x, float y) {
    unsigned long long r;
    asm("mov.b64 %0, {%1, %2};" : "=l"(r) : "f"(x), "f"(y));
    return r;
}
__device__ __forceinline__ float2 upk2(unsigned long long v) {
    float2 f;
    asm("mov.b64 {%0, %1}, %2;" : "=f"(f.x), "=f"(f.y) : "l"(v));
    return f;
}
__device__ __forceinline__ unsigned long long fma2(unsigned long long a,
                                                   unsigned long long b,
                                                   unsigned long long c) {
    unsigned long long d;
    asm("fma.rn.f32x2 %0, %1, %2, %3;" : "=l"(d) : "l"(a), "l"(b), "l"(c));
    return d;
}

#define QK_BLOCKS (NREV / 32)            // 128 CTAs, 32 reviews each
#define RPS_STRIDE 201                   // odd stride -> conflict-free lane reads
#define QK_SM_WORDS (DW * DW + 32 * RPS_STRIDE)   // 40000 + 6432 = 46432

// ---------------- K1: q = rev_pos @ M_w  (+ fused prep blocks) ----------------
// v5: reviews on LANES, d-chunks on warps. m-loads are warp-uniform SMEM
// broadcasts (crossbar redundancy 8x -> 1x); r-loads conflict-free (stride 201).
__global__ __launch_bounds__(512, 1)
void qk(const float* __restrict__ rp, const float* __restrict__ Mw,
        const float* __restrict__ Ww, const float* __restrict__ Tw,
        const int* __restrict__ usi, const int* __restrict__ isi, int F) {
    int tid = threadIdx.x, w = tid >> 5, lane = tid & 31;

    // -------- prep blocks: bf16 weights + segment boundaries --------
    if (blockIdx.x >= QK_BLOCKS) {
        int i = (blockIdx.x - QK_BLOCKS) * 512 + tid;
        if (i < AASP * DW) {
            g_Wwb[i] = __float2bfloat16(Ww[i]);
            g_Twb[i] = __float2bfloat16(Tw[i]);
        }
        if (i < F) {
            int u = usi[i];
            if (i == 0 || usi[i - 1] != u) g_ubnd[u] = i;
            int v = isi[i];
            if (i == 0 || isi[i - 1] != v) g_ibnd[v] = i;
        }
        if (i == 0) { g_ubnd[BUSR] = F; g_ibnd[BUSR] = F; }
        return;
    }

    extern __shared__ float sm[];
    float* Ms  = sm;                 // 40000 floats (fp32, exact)
    float* rps = sm + DW * DW;       // 32 x 201 padded
    int n0 = blockIdx.x * 32;
    {
        const float4* Mw4 = (const float4*)Mw;
        float4* Ms4w = (float4*)Ms;
        for (int i = tid; i < DW * DW / 4; i += 512) Ms4w[i] = __ldg(&Mw4[i]);
        for (int i = tid; i < 32 * DW; i += 512) {
            int row = i / DW, col = i - row * DW;
            rps[row * RPS_STRIDE + col] = __ldg(&rp[n0 * DW + i]);
        }
    }
    __syncthreads();

    // warp w owns float4-chunks {w, w+16, w+32} and (w<2) w+48  (50 chunks total)
    const ulonglong2* Ms2 = (const ulonglong2*)Ms;
    int nchunks = (w < 2) ? 4 : 3;

    unsigned long long acc[4][2];
    #pragma unroll
    for (int k = 0; k < 4; k++) { acc[k][0] = 0ull; acc[k][1] = 0ull; }

    const float* rrow = rps + lane * RPS_STRIDE;
    #pragma unroll 2
    for (int d2 = 0; d2 < DW; d2++) {
        float r = rrow[d2];                       // conflict-free (stride 201)
        unsigned long long rr = pk2(r, r);
        ulonglong2 m[4];
        m[0] = Ms2[d2 * 50 + w];                  // broadcast (warp-uniform)
        m[1] = Ms2[d2 * 50 + w + 16];
        m[2] = Ms2[d2 * 50 + w + 32];
        if (w < 2) m[3] = Ms2[d2 * 50 + w + 48];
        #pragma unroll
        for (int k = 0; k < 3; k++) {
            acc[k][0] = fma2(rr, m[k].x, acc[k][0]);
            acc[k][1] = fma2(rr, m[k].y, acc[k][1]);
        }
        if (w < 2) {
            acc[3][0] = fma2(rr, m[3].x, acc[3][0]);
            acc[3][1] = fma2(rr, m[3].y, acc[3][1]);
        }
    }

    {   // write-out: lane = review, chunk = w + 16k
        float4* gq4 = (float4*)g_q;
        int row = (n0 + lane) * 50;
        #pragma unroll
        for (int k = 0; k < 4; k++) {
            if (k < nchunks) {
                float2 a0 = upk2(acc[k][0]), a1 = upk2(acc[k][1]);
                float4 o; o.x = a0.x; o.y = a0.y; o.z = a1.x; o.w = a1.y;
                gq4[row + w + 16 * k] = o;
            }
        }
    }
}

// ---------------- K2: fused per-review ABAE, bf16 SMEM tile, occ 4 ------------
#define SM_WORDS 13608

__global__ __launch_bounds__(256, 4)
void mainkern(const int* __restrict__ hist, const float* __restrict__ wemb,
              const float* __restrict__ rneg, const float* __restrict__ Wb,
              const float* __restrict__ Tw) {
    extern __shared__ float sm[];
    int n = blockIdx.x;
    int tid = threadIdx.x, w = tid >> 5, lane = tid & 31;

    // -------- extra block: U_loss (exact fp32 Tw) --------
    if (n == NREV) {
        float* Ts  = sm;          // 6400
        float* nrm = sm + 6400;   // 32
        float* red = sm + 6432;   // 8
        for (int i = tid; i < DW * AASP; i += 256) Ts[i] = Tw[i];
        __syncthreads();
        if (tid < AASP) {
            float s = 0.f;
            for (int d = 0; d < DW; d++) { float v = Ts[d * AASP + tid]; s += v * v; }
            nrm[tid] = fmaxf(sqrtf(s), 1e-12f);
        }
        __syncthreads();
        float part = 0.f;
        for (int pr = tid; pr < AASP * AASP; pr += 256) {
            int a = pr >> 5, b = pr & 31;
            float s = 0.f;
            for (int d = 0; d < DW; d++) s += Ts[d * AASP + a] * Ts[d * AASP + b];
            float g = s / (nrm[a] * nrm[b]);
            float diff = g - ((a == b) ? 1.f : 0.f);
            part += diff * diff;
        }
        float v = warp_sum(part);
        if (lane == 0) red[w] = v;
        __syncthreads();
        if (tid == 0) {
            float t = 0.f;
            for (int k = 0; k < 8; k++) t += red[k];
            g_U[0] = t / (float)(AASP * AASP);
        }
        return;
    }

    uint2* eb2  = (uint2*)sm;
    float* qs   = sm + 12800;
    float* ax   = sm + 13000;
    float* zs   = sm + 13128;
    float* p    = sm + 13328;
    float* part = sm + 13360;
    float* tot  = sm + 13464;
    int*   tok  = (int*)(sm + 13480);

    if (tid < LTOK) tok[tid] = hist[n * LTOK + tid];
    if (tid < DW)   qs[tid]  = g_q[n * DW + tid];
    __syncthreads();

    bool hi = (lane < 18);
    const float4* qs4 = (const float4*)qs;
    float4 qv0 = qs4[lane];
    float4 qv1 = hi ? qs4[32 + lane] : make_float4(0, 0, 0, 0);
    const float4* we4 = (const float4*)wemb;

    // -------- single gather + dx (fp32 exact) + bf16 tile store --------
    #pragma unroll
    for (int t0 = 0; t0 < 16; t0 += 4) {
        float4 v0[4], v1[4];
        #pragma unroll
        for (int t = 0; t < 4; t++) {
            int rb = tok[w * 16 + t0 + t] * 50;
            v0[t] = __ldg(&we4[rb + lane]);
            v1[t] = hi ? __ldg(&we4[rb + 32 + lane]) : make_float4(0, 0, 0, 0);
        }
        float a[4];
        #pragma unroll
        for (int t = 0; t < 4; t++) {
            int l = w * 16 + t0 + t;
            eb2[l * 50 + lane] = pack_bf16x4(v0[t]);
            if (hi) eb2[l * 50 + 32 + lane] = pack_bf16x4(v1[t]);
            a[t] = dot4(v0[t], qv0) + dot4(v1[t], qv1);
        }
        #pragma unroll
        for (int t = 0; t < 4; t++) a[t] = warp_sum(a[t]);
        if (lane == 0) {
            #pragma unroll
            for (int t = 0; t < 4; t++) ax[w * 16 + t0 + t] = a[t];
        }
    }
    __syncthreads();

    // -------- softmax over 128 tokens (warp 0) --------
    if (w == 0) {
        float v0 = ax[lane], v1 = ax[lane + 32], v2 = ax[lane + 64], v3 = ax[lane + 96];
        float m = fmaxf(fmaxf(v0, v1), fmaxf(v2, v3));
        #pragma unroll
        for (int o = 16; o; o >>= 1) m = fmaxf(m, __shfl_xor_sync(0xffffffffu, m, o));
        v0 = __expf(v0 - m); v1 = __expf(v1 - m);
        v2 = __expf(v2 - m); v3 = __expf(v3 - m);
        float s = (v0 + v1) + (v2 + v3);
        #pragma unroll
        for (int o = 16; o; o >>= 1) s += __shfl_xor_sync(0xffffffffu, s, o);
        float inv = 1.f / s;
        ax[lane] = v0 * inv; ax[lane + 32] = v1 * inv;
        ax[lane + 64] = v2 * inv; ax[lane + 96] = v3 * inv;
    }
    __syncthreads();

    // -------- z_s from bf16 SMEM tile (reshape trick, flat slices) --------
    {
        const float4* ax4 = (const float4*)ax;
        float4 av = ax4[lane];
        #pragma unroll
        for (int j0 = 0; j0 < 24; j0 += 4) {
            float a[4];
            #pragma unroll
            for (int k = 0; k < 4; k++) {
                int d = w + 8 * (j0 + k);
                uint2 u = eb2[d * 32 + lane];
                float2 f0 = bf2f(u.x), f1 = bf2f(u.y);
                a[k] = f0.x * av.x + f0.y * av.y + f1.x * av.z + f1.y * av.w;
            }
            #pragma unroll
            for (int k = 0; k < 4; k++) a[k] = warp_sum(a[k]);
            if (lane == 0) {
                #pragma unroll
                for (int k = 0; k < 4; k++) zs[w + 8 * (j0 + k)] = a[k];
            }
        }
        {   // leftover d = 192 + w
            int d = 192 + w;
            uint2 u = eb2[d * 32 + lane];
            float2 f0 = bf2f(u.x), f1 = bf2f(u.y);
            float a = warp_sum(f0.x * av.x + f0.y * av.y + f1.x * av.z + f1.y * av.w);
            if (lane == 0) zs[d] = a;
        }
    }
    __syncthreads();

    // -------- prefetch negatives (consumed in final phase) --------
    float ng[NNEG];
    #pragma unroll
    for (int k = 0; k < NNEG; k++)
        ng[k] = (tid < DW) ? __ldg(&rneg[(n * NNEG + k) * DW + tid]) : 0.f;

    // -------- logits = z_s @ W_w^T + W_b (bf16 weights) --------
    {
        const float4* zs4 = (const float4*)zs;
        float4 zv0 = zs4[lane];
        float4 zv1 = hi ? zs4[32 + lane] : make_float4(0, 0, 0, 0);
        const uint2* wb2 = (const uint2*)g_Wwb;
        #pragma unroll
        for (int j = 0; j < 4; j++) {
            int a = w + 8 * j;
            uint2 u0 = __ldg(&wb2[a * 50 + lane]);
            float2 w0 = bf2f(u0.x), w1 = bf2f(u0.y);
            float acc = w0.x * zv0.x + w0.y * zv0.y + w1.x * zv0.z + w1.y * zv0.w;
            if (hi) {
                uint2 u1 = __ldg(&wb2[a * 50 + 32 + lane]);
                float2 w2 = bf2f(u1.x), w3 = bf2f(u1.y);
                acc += w2.x * zv1.x + w2.y * zv1.y + w3.x * zv1.z + w3.y * zv1.w;
            }
            acc = warp_sum(acc);
            if (lane == 0) p[a] = acc + Wb[a];
        }
    }
    __syncthreads();

    // -------- softmax over A=32 (warp 0) --------
    if (w == 0) {
        float v = p[lane];
        float m = v;
        #pragma unroll
        for (int o = 16; o; o >>= 1) m = fmaxf(m, __shfl_xor_sync(0xffffffffu, m, o));
        float ex = __expf(v - m);
        float s = ex;
        #pragma unroll
        for (int o = 16; o; o >>= 1) s += __shfl_xor_sync(0xffffffffu, s, o);
        p[lane] = ex / s;
    }
    __syncthreads();

    // -------- r_s = p @ T_w^T (bf16 Tw row) ; 13 fused dots --------
    float rsv = 0.f, zsv = 0.f;
    if (tid < DW) {
        const uint4* tb4 = (const uint4*)(g_Twb + tid * AASP);
        float acc = 0.f;
        #pragma unroll
        for (int j = 0; j < 4; j++) {
            uint4 t = __ldg(&tb4[j]);
            float2 a0 = bf2f(t.x), a1 = bf2f(t.y), a2 = bf2f(t.z), a3 = bf2f(t.w);
            acc += a0.x * p[j * 8 + 0] + a0.y * p[j * 8 + 1]
                 + a1.x * p[j * 8 + 2] + a1.y * p[j * 8 + 3]
                 + a2.x * p[j * 8 + 4] + a2.y * p[j * 8 + 5]
                 + a3.x * p[j * 8 + 6] + a3.y * p[j * 8 + 7];
        }
        g_rs[n * DW + tid] = acc;
        rsv = acc;
        zsv = zs[tid];
    }

    float v[13];
    v[0] = zsv * zsv; v[1] = rsv * rsv; v[2] = zsv * rsv;
    #pragma unroll
    for (int k = 0; k < NNEG; k++) { v[3 + k] = ng[k] * ng[k]; v[8 + k] = ng[k] * rsv; }
    #pragma unroll
    for (int x = 0; x < 13; x++) v[x] = warp_sum(v[x]);
    if (lane == 0) {
        #pragma unroll
        for (int x = 0; x < 13; x++) part[w * 13 + x] = v[x];
    }
    __syncthreads();
    if (w == 0 && lane < 13) {
        float s = 0.f;
        #pragma unroll
        for (int k = 0; k < 8; k++) s += part[k * 13 + lane];
        tot[lane] = s;
    }
    __syncthreads();
    if (tid == 0) {
        float nz = fmaxf(sqrtf(tot[0]), 1e-12f);
        float nr = fmaxf(sqrtf(tot[1]), 1e-12f);
        float c1 = tot[2] / (nz * nr);
        float h = 0.f;
        #pragma unroll
        for (int k = 0; k < NNEG; k++) {
            float c2 = tot[8 + k] / (fmaxf(sqrtf(tot[3 + k]), 1e-12f) * nr);
            h += fmaxf(0.f, c2 - c1);
        }
        g_hinge[n] = h;
    }
}

// ---------------- K3: segment means + prediction + final reduce ---------------
__global__ __launch_bounds__(256, 8)
void segpred(const int* __restrict__ uhi, const int* __restrict__ ihi,
             const float* __restrict__ label, float* __restrict__ out) {
    int b = blockIdx.x;
    int tid = threadIdx.x, w = tid >> 5, lane = tid & 31;
    __shared__ int sidx[96];
    __shared__ int meta[4];
    __shared__ float red[8];
    __shared__ unsigned int rank;

    if (w < 2) {
        const int* bnd = w ? g_ibnd : g_ubnd;
        const int* idx = w ? ihi : uhi;
        int lo = bnd[b], hi2 = bnd[b + 1];
        int cnt = hi2 - lo;
        if (lane == 0) { meta[w] = cnt; meta[2 + w] = lo; }
        for (int j = lane; j < cnt && j < 48; j += 32)
            sidx[w * 48 + j] = idx[lo + j];
    }
    __syncthreads();

    int cu = meta[0], ci = meta[1];
    float prod = 0.f;
    int d = tid;
    if (d < DW) {
        float u0 = 0.f, u1 = 0.f, u2 = 0.f, u3 = 0.f;
        float i0 = 0.f, i1 = 0.f, i2 = 0.f, i3 = 0.f;
        int cuc = cu < 48 ? cu : 48;
        int cic = ci < 48 ? ci : 48;
        int c = cuc < cic ? cuc : cic;
        int j = 0;
        for (; j + 4 <= c; j += 4) {
            u0 += g_rs[sidx[j]      * DW + d];
            i0 += g_rs[sidx[48 + j] * DW + d];
            u1 += g_rs[sidx[j + 1]      * DW + d];
            i1 += g_rs[sidx[48 + j + 1] * DW + d];
            u2 += g_rs[sidx[j + 2]      * DW + d];
            i2 += g_rs[sidx[48 + j + 2] * DW + d];
            u3 += g_rs[sidx[j + 3]      * DW + d];
            i3 += g_rs[sidx[48 + j + 3] * DW + d];
        }
        for (int k = j; k < cuc; k++) u0 += g_rs[sidx[k] * DW + d];
        for (int k = j; k < cic; k++) i0 += g_rs[sidx[48 + k] * DW + d];
        for (int k = 48; k < cu; k++) u0 += g_rs[uhi[meta[2] + k] * DW + d];
        for (int k = 48; k < ci; k++) i0 += g_rs[ihi[meta[3] + k] * DW + d];
        float um = ((u0 + u1) + (u2 + u3)) / (float)cu;
        float im = ((i0 + i1) + (i2 + i3)) / (float)ci;
        prod = um * im;
    }
    float s = warp_sum(prod);
    if (lane == 0) red[w] = s;
    __syncthreads();
    if (tid == 0) {
        float t = 0.f;
        #pragma unroll
        for (int k = 0; k < 8; k++) t += red[k];
        float e = t + 3.5f - label[b];
        g_sq[b] = e * e;
        __threadfence();
        rank = atomicAdd(&g_cnt, 1u);
    }
    __syncthreads();

    if (rank == BUSR - 1) {
        __threadfence();
        const float4* h4 = (const float4*)g_hinge;
        float hsum = 0.f;
        #pragma unroll
        for (int r = 0; r < 4; r++) {
            float4 hv = h4[tid + 256 * r];
            hsum += (hv.x + hv.y) + (hv.z + hv.w);
        }
        hsum = warp_sum(hsum);
        if (lane == 0) red[w] = hsum;
        __syncthreads();
        float hs = 0.f;
        if (tid == 0) {
            #pragma unroll
            for (int k = 0; k < 8; k++) hs += red[k];
        }
        __syncthreads();

        float4 qv = ((const float4*)g_sq)[tid];
        float q = (qv.x + qv.y) + (qv.z + qv.w);
        q = warp_sum(q);
        if (lane == 0) red[w] = q;
        __syncthreads();
        if (tid == 0) {
            float rsum = 0.f;
            #pragma unroll
            for (int k = 0; k < 8; k++) rsum += red[k];
            float rating = rsum / (float)BUSR;
            float J = hs / (float)(NREV * NNEG);
            float abae = g_U[0] + J;
            out[0] = rating + abae;
            out[1] = rating;
            out[2] = abae;
            g_cnt = 0u;
        }
    }
}

// ---------------- launch ------------------------------------------------------
extern "C" void kernel_launch(void* const* d_in, const int* in_sizes, int n_in,
                              void* d_out, int out_size) {
    const int*   hist  = (const int*)d_in[0];
    const float* rpos  = (const float*)d_in[1];
    const float* rneg  = (const float*)d_in[2];
    const float* label = (const float*)d_in[5];
    const int*   uhi   = (const int*)d_in[6];
    const int*   usi   = (const int*)d_in[7];
    const int*   ihi   = (const int*)d_in[8];
    const int*   isi   = (const int*)d_in[9];
    const float* wemb  = (const float*)d_in[10];
    const float* Mw    = (const float*)d_in[11];
    const float* Ww    = (const float*)d_in[12];
    const float* Wb    = (const float*)d_in[13];
    const float* Tw    = (const float*)d_in[14];
    float* out = (float*)d_out;
    int F = in_sizes[6];

    const int SMEM_QK   = QK_SM_WORDS * 4;           // 185728 B
    const int SMEM_MAIN = SM_WORDS * 4;              // 54432 B
    cudaFuncSetAttribute(qk, cudaFuncAttributeMaxDynamicSharedMemorySize, SMEM_QK);
    cudaFuncSetAttribute(mainkern, cudaFuncAttributeMaxDynamicSharedMemorySize, SMEM_MAIN);

    int prep_elems = (AASP * DW > F) ? AASP * DW : F;
    int prep_blocks = (prep_elems + 511) / 512;
    qk<<<QK_BLOCKS + prep_blocks, 512, SMEM_QK>>>(rpos, Mw, Ww, Tw, usi, isi, F);
    mainkern<<<NREV + 1, 256, SMEM_MAIN>>>(hist, wemb, rneg, Wb, Tw);
    segpred<<<BUSR, 256>>>(uhi, ihi, label, out);
}

// round 16
// speedup vs baseline: 1.0298x; 1.0296x over previous
#include <cuda_runtime.h>
#include <cuda_bf16.h>
#include <math.h>

#define NREV 4096
#define LTOK 128
#define DW   200
#define AASP 32
#define NNEG 5
#define BUSR 1024

// ---------------- scratch (device globals) -----------------------------------
__device__ __align__(16) float g_q[NREV * DW];
__device__ __align__(16) float g_rs[NREV * DW];
__device__ __align__(16) float g_hinge[NREV];
__device__ __align__(16) float g_sq[BUSR];
__device__ float g_U[1];
__device__ __align__(16) __nv_bfloat16 g_Wwb[AASP * DW];
__device__ __align__(16) __nv_bfloat16 g_Twb[DW * AASP];
__device__ int g_ubnd[BUSR + 1];
__device__ int g_ibnd[BUSR + 1];
__device__ unsigned int g_cnt;

__device__ __forceinline__ float dot4(float4 a, float4 b) {
    return a.x * b.x + a.y * b.y + a.z * b.z + a.w * b.w;
}
__device__ __forceinline__ float warp_sum(float v) {
    #pragma unroll
    for (int o = 16; o; o >>= 1) v += __shfl_down_sync(0xffffffffu, v, o);
    return v;
}
__device__ __forceinline__ uint2 pack_bf16x4(float4 v) {
    __nv_bfloat162 a = __float22bfloat162_rn(make_float2(v.x, v.y));
    __nv_bfloat162 b = __float22bfloat162_rn(make_float2(v.z, v.w));
    uint2 u;
    u.x = *(unsigned int*)&a;
    u.y = *(unsigned int*)&b;
    return u;
}
__device__ __forceinline__ float2 bf2f(unsigned int u) {
    return __bfloat1622float2(*(__nv_bfloat162*)&u);
}
// ---- f32x2 packed math (sm_103a) ----
__device__ __forceinline__ unsigned long long pk2(float x, float y) {
    unsigned long long r;
    asm("mov.b64 %0, {%1, %2};" : "=l"(r) : "f"(x), "f"(y));
    return r;
}
__device__ __forceinline__ float2 upk2(unsigned long long v) {
    float2 f;
    asm("mov.b64 {%0, %1}, %2;" : "=f"(f.x), "=f"(f.y) : "l"(v));
    return f;
}
__device__ __forceinline__ unsigned long long fma2(unsigned long long a,
                                                   unsigned long long b,
                                                   unsigned long long c) {
    unsigned long long d;
    asm("fma.rn.f32x2 %0, %1, %2, %3;" : "=l"(d) : "l"(a), "l"(b), "l"(c));
    return d;
}

#define QK_BLOCKS (NREV / 32)   // 128 CTAs, 32 reviews each

// ---------------- K1: q = rev_pos @ M_w  (+ fused prep blocks) ----------------
// Round-12 v2 design: 512 threads, Ms+rps staged in SMEM, warp = 4 reviews x
// one output half, f32x2 packed FMA. (3 rewrites failed to beat this.)
__global__ __launch_bounds__(512, 1)
void qk(const float* __restrict__ rp, const float* __restrict__ Mw,
        const float* __restrict__ Ww, const float* __restrict__ Tw,
        const int* __restrict__ usi, const int* __restrict__ isi, int F) {
    int tid = threadIdx.x, w = tid >> 5, lane = tid & 31;

    // -------- prep blocks: bf16 weights + segment boundaries --------
    if (blockIdx.x >= QK_BLOCKS) {
        int i = (blockIdx.x - QK_BLOCKS) * 512 + tid;
        if (i < AASP * DW) {
            g_Wwb[i] = __float2bfloat16(Ww[i]);
            g_Twb[i] = __float2bfloat16(Tw[i]);
        }
        if (i < F) {
            int u = usi[i];
            if (i == 0 || usi[i - 1] != u) g_ubnd[u] = i;
            int v = isi[i];
            if (i == 0 || isi[i - 1] != v) g_ibnd[v] = i;
        }
        if (i == 0) { g_ubnd[BUSR] = F; g_ibnd[BUSR] = F; }
        return;
    }

    extern __shared__ float sm[];
    float* Ms  = sm;            // 40000
    float* rps = sm + DW * DW;  // 6400
    {
        const float4* Mw4 = (const float4*)Mw;
        float4* Ms4w = (float4*)Ms;
        for (int i = tid; i < DW * DW / 4; i += 512) Ms4w[i] = __ldg(&Mw4[i]);
        int n0 = blockIdx.x * 32;
        const float4* rp4 = (const float4*)(rp + n0 * DW);
        float4* rps4w = (float4*)rps;
        for (int i = tid; i < 32 * DW / 4; i += 512) rps4w[i] = __ldg(&rp4[i]);
    }
    __syncthreads();

    int wg = w & 7;
    int h  = w >> 3;
    bool act = (h == 0) || (lane < 18);
    int c = h ? (32 + (lane < 18 ? lane : 0)) : lane;

    const float4* Ms4  = (const float4*)Ms;
    const float4* rps4 = (const float4*)rps;

    unsigned long long acc[4][2];
    #pragma unroll
    for (int j = 0; j < 4; j++) { acc[j][0] = 0ull; acc[j][1] = 0ull; }

    for (int d2b = 0; d2b < 50; d2b++) {
        float4 r4[4];
        #pragma unroll
        for (int j = 0; j < 4; j++) r4[j] = rps4[(wg * 4 + j) * 50 + d2b];
        #pragma unroll
        for (int s = 0; s < 4; s++) {
            float4 m = Ms4[(d2b * 4 + s) * 50 + c];
            unsigned long long m01 = pk2(m.x, m.y), m23 = pk2(m.z, m.w);
            #pragma unroll
            for (int j = 0; j < 4; j++) {
                float r = (s == 0) ? r4[j].x : (s == 1) ? r4[j].y
                        : (s == 2) ? r4[j].z : r4[j].w;
                unsigned long long rr = pk2(r, r);
                acc[j][0] = fma2(rr, m01, acc[j][0]);
                acc[j][1] = fma2(rr, m23, acc[j][1]);
            }
        }
    }

    if (act) {
        int n0 = blockIdx.x * 32;
        float4* gq4 = (float4*)g_q;
        #pragma unroll
        for (int j = 0; j < 4; j++) {
            float2 a0 = upk2(acc[j][0]), a1 = upk2(acc[j][1]);
            float4 o; o.x = a0.x; o.y = a0.y; o.z = a1.x; o.w = a1.y;
            gq4[(n0 + wg * 4 + j) * 50 + c] = o;
        }
    }
}

// ---------------- K2: fused per-review ABAE, bf16 SMEM tile, occ 4 ------------
// Change vs round 12: both softmaxes computed redundantly per-warp (no warp-0
// serialization, 2 barriers removed); r_s reads p via warp shfl broadcast.
#define SM_WORDS 13608

__global__ __launch_bounds__(256, 4)
void mainkern(const int* __restrict__ hist, const float* __restrict__ wemb,
              const float* __restrict__ rneg, const float* __restrict__ Wb,
              const float* __restrict__ Tw) {
    extern __shared__ float sm[];
    int n = blockIdx.x;
    int tid = threadIdx.x, w = tid >> 5, lane = tid & 31;

    // -------- extra block: U_loss (exact fp32 Tw) --------
    if (n == NREV) {
        float* Ts  = sm;          // 6400
        float* nrm = sm + 6400;   // 32
        float* red = sm + 6432;   // 8
        for (int i = tid; i < DW * AASP; i += 256) Ts[i] = Tw[i];
        __syncthreads();
        if (tid < AASP) {
            float s = 0.f;
            for (int d = 0; d < DW; d++) { float v = Ts[d * AASP + tid]; s += v * v; }
            nrm[tid] = fmaxf(sqrtf(s), 1e-12f);
        }
        __syncthreads();
        float part = 0.f;
        for (int pr = tid; pr < AASP * AASP; pr += 256) {
            int a = pr >> 5, b = pr & 31;
            float s = 0.f;
            for (int d = 0; d < DW; d++) s += Ts[d * AASP + a] * Ts[d * AASP + b];
            float g = s / (nrm[a] * nrm[b]);
            float diff = g - ((a == b) ? 1.f : 0.f);
            part += diff * diff;
        }
        float v = warp_sum(part);
        if (lane == 0) red[w] = v;
        __syncthreads();
        if (tid == 0) {
            float t = 0.f;
            for (int k = 0; k < 8; k++) t += red[k];
            g_U[0] = t / (float)(AASP * AASP);
        }
        return;
    }

    uint2* eb2  = (uint2*)sm;
    float* qs   = sm + 12800;
    float* ax   = sm + 13000;
    float* zs   = sm + 13128;
    float* p    = sm + 13328;
    float* part = sm + 13360;
    float* tot  = sm + 13464;
    int*   tok  = (int*)(sm + 13480);

    if (tid < LTOK) tok[tid] = hist[n * LTOK + tid];
    if (tid < DW)   qs[tid]  = g_q[n * DW + tid];
    __syncthreads();

    bool hi = (lane < 18);
    const float4* qs4 = (const float4*)qs;
    float4 qv0 = qs4[lane];
    float4 qv1 = hi ? qs4[32 + lane] : make_float4(0, 0, 0, 0);
    const float4* we4 = (const float4*)wemb;

    // -------- single gather + dx (fp32 exact) + bf16 tile store --------
    #pragma unroll
    for (int t0 = 0; t0 < 16; t0 += 4) {
        float4 v0[4], v1[4];
        #pragma unroll
        for (int t = 0; t < 4; t++) {
            int rb = tok[w * 16 + t0 + t] * 50;
            v0[t] = __ldg(&we4[rb + lane]);
            v1[t] = hi ? __ldg(&we4[rb + 32 + lane]) : make_float4(0, 0, 0, 0);
        }
        float a[4];
        #pragma unroll
        for (int t = 0; t < 4; t++) {
            int l = w * 16 + t0 + t;
            eb2[l * 50 + lane] = pack_bf16x4(v0[t]);
            if (hi) eb2[l * 50 + 32 + lane] = pack_bf16x4(v1[t]);
            a[t] = dot4(v0[t], qv0) + dot4(v1[t], qv1);
        }
        #pragma unroll
        for (int t = 0; t < 4; t++) a[t] = warp_sum(a[t]);
        if (lane == 0) {
            #pragma unroll
            for (int t = 0; t < 4; t++) ax[w * 16 + t0 + t] = a[t];
        }
    }
    __syncthreads();

    // -------- softmax over 128 tokens: redundant per-warp, result in regs -----
    float4 av;
    {
        const float4* ax4 = (const float4*)ax;
        float4 axv = ax4[lane];
        float m = fmaxf(fmaxf(axv.x, axv.y), fmaxf(axv.z, axv.w));
        #pragma unroll
        for (int o = 16; o; o >>= 1) m = fmaxf(m, __shfl_xor_sync(0xffffffffu, m, o));
        float e0 = __expf(axv.x - m), e1 = __expf(axv.y - m);
        float e2 = __expf(axv.z - m), e3 = __expf(axv.w - m);
        float s = (e0 + e1) + (e2 + e3);
        #pragma unroll
        for (int o = 16; o; o >>= 1) s += __shfl_xor_sync(0xffffffffu, s, o);
        float inv = 1.f / s;
        av = make_float4(e0 * inv, e1 * inv, e2 * inv, e3 * inv);
    }
    // no barrier needed: av is register-resident, tile already synced

    // -------- z_s from bf16 SMEM tile (reshape trick, flat slices) --------
    {
        #pragma unroll
        for (int j0 = 0; j0 < 24; j0 += 4) {
            float a[4];
            #pragma unroll
            for (int k = 0; k < 4; k++) {
                int d = w + 8 * (j0 + k);
                uint2 u = eb2[d * 32 + lane];
                float2 f0 = bf2f(u.x), f1 = bf2f(u.y);
                a[k] = f0.x * av.x + f0.y * av.y + f1.x * av.z + f1.y * av.w;
            }
            #pragma unroll
            for (int k = 0; k < 4; k++) a[k] = warp_sum(a[k]);
            if (lane == 0) {
                #pragma unroll
                for (int k = 0; k < 4; k++) zs[w + 8 * (j0 + k)] = a[k];
            }
        }
        {   // leftover d = 192 + w
            int d = 192 + w;
            uint2 u = eb2[d * 32 + lane];
            float2 f0 = bf2f(u.x), f1 = bf2f(u.y);
            float a = warp_sum(f0.x * av.x + f0.y * av.y + f1.x * av.z + f1.y * av.w);
            if (lane == 0) zs[d] = a;
        }
    }
    __syncthreads();

    // -------- prefetch negatives (consumed in final phase) --------
    float ng[NNEG];
    #pragma unroll
    for (int k = 0; k < NNEG; k++)
        ng[k] = (tid < DW) ? __ldg(&rneg[(n * NNEG + k) * DW + tid]) : 0.f;

    // -------- logits = z_s @ W_w^T + W_b (bf16 weights) --------
    {
        const float4* zs4 = (const float4*)zs;
        float4 zv0 = zs4[lane];
        float4 zv1 = hi ? zs4[32 + lane] : make_float4(0, 0, 0, 0);
        const uint2* wb2 = (const uint2*)g_Wwb;
        #pragma unroll
        for (int j = 0; j < 4; j++) {
            int a = w + 8 * j;
            uint2 u0 = __ldg(&wb2[a * 50 + lane]);
            float2 w0 = bf2f(u0.x), w1 = bf2f(u0.y);
            float acc = w0.x * zv0.x + w0.y * zv0.y + w1.x * zv0.z + w1.y * zv0.w;
            if (hi) {
                uint2 u1 = __ldg(&wb2[a * 50 + 32 + lane]);
                float2 w2 = bf2f(u1.x), w3 = bf2f(u1.y);
                acc += w2.x * zv1.x + w2.y * zv1.y + w3.x * zv1.z + w3.y * zv1.w;
            }
            acc = warp_sum(acc);
            if (lane == 0) p[a] = acc + Wb[a];
        }
    }
    __syncthreads();

    // -------- softmax over A=32: redundant per-warp (no barrier) --------
    float pv;
    {
        float v = p[lane];
        float m = v;
        #pragma unroll
        for (int o = 16; o; o >>= 1) m = fmaxf(m, __shfl_xor_sync(0xffffffffu, m, o));
        float ex = __expf(v - m);
        float s = ex;
        #pragma unroll
        for (int o = 16; o; o >>= 1) s += __shfl_xor_sync(0xffffffffu, s, o);
        pv = ex / s;
    }

    // -------- r_s = p @ T_w^T (bf16 Tw row; p via warp shfl broadcast) --------
    // Executed warp-uniform (clamped index) so shfl is legal; stores guarded.
    float rsv = 0.f, zsv = 0.f;
    {
        int td = (tid < DW) ? tid : 0;
        const uint4* tb4 = (const uint4*)(g_Twb + td * AASP);
        float acc = 0.f;
        #pragma unroll
        for (int j = 0; j < 4; j++) {
            uint4 t = __ldg(&tb4[j]);
            float2 a0 = bf2f(t.x), a1 = bf2f(t.y), a2 = bf2f(t.z), a3 = bf2f(t.w);
            acc += a0.x * __shfl_sync(0xffffffffu, pv, j * 8 + 0)
                 + a0.y * __shfl_sync(0xffffffffu, pv, j * 8 + 1)
                 + a1.x * __shfl_sync(0xffffffffu, pv, j * 8 + 2)
                 + a1.y * __shfl_sync(0xffffffffu, pv, j * 8 + 3)
                 + a2.x * __shfl_sync(0xffffffffu, pv, j * 8 + 4)
                 + a2.y * __shfl_sync(0xffffffffu, pv, j * 8 + 5)
                 + a3.x * __shfl_sync(0xffffffffu, pv, j * 8 + 6)
                 + a3.y * __shfl_sync(0xffffffffu, pv, j * 8 + 7);
        }
        if (tid < DW) {
            g_rs[n * DW + tid] = acc;
            rsv = acc;
            zsv = zs[tid];
        }
    }

    float v[13];
    v[0] = zsv * zsv; v[1] = rsv * rsv; v[2] = zsv * rsv;
    #pragma unroll
    for (int k = 0; k < NNEG; k++) { v[3 + k] = ng[k] * ng[k]; v[8 + k] = ng[k] * rsv; }
    #pragma unroll
    for (int x = 0; x < 13; x++) v[x] = warp_sum(v[x]);
    if (lane == 0) {
        #pragma unroll
        for (int x = 0; x < 13; x++) part[w * 13 + x] = v[x];
    }
    __syncthreads();
    if (w == 0 && lane < 13) {
        float s = 0.f;
        #pragma unroll
        for (int k = 0; k < 8; k++) s += part[k * 13 + lane];
        tot[lane] = s;
    }
    __syncthreads();
    if (tid == 0) {
        float nz = fmaxf(sqrtf(tot[0]), 1e-12f);
        float nr = fmaxf(sqrtf(tot[1]), 1e-12f);
        float c1 = tot[2] / (nz * nr);
        float h = 0.f;
        #pragma unroll
        for (int k = 0; k < NNEG; k++) {
            float c2 = tot[8 + k] / (fmaxf(sqrtf(tot[3 + k]), 1e-12f) * nr);
            h += fmaxf(0.f, c2 - c1);
        }
        g_hinge[n] = h;
    }
}

// ---------------- K3: segment means + prediction + final reduce ---------------
__global__ __launch_bounds__(256, 8)
void segpred(const int* __restrict__ uhi, const int* __restrict__ ihi,
             const float* __restrict__ label, float* __restrict__ out) {
    int b = blockIdx.x;
    int tid = threadIdx.x, w = tid >> 5, lane = tid & 31;
    __shared__ int sidx[96];
    __shared__ int meta[4];
    __shared__ float red[8];
    __shared__ unsigned int rank;

    if (w < 2) {
        const int* bnd = w ? g_ibnd : g_ubnd;
        const int* idx = w ? ihi : uhi;
        int lo = bnd[b], hi2 = bnd[b + 1];
        int cnt = hi2 - lo;
        if (lane == 0) { meta[w] = cnt; meta[2 + w] = lo; }
        for (int j = lane; j < cnt && j < 48; j += 32)
            sidx[w * 48 + j] = idx[lo + j];
    }
    __syncthreads();

    int cu = meta[0], ci = meta[1];
    float prod = 0.f;
    int d = tid;
    if (d < DW) {
        float u0 = 0.f, u1 = 0.f, u2 = 0.f, u3 = 0.f;
        float i0 = 0.f, i1 = 0.f, i2 = 0.f, i3 = 0.f;
        int cuc = cu < 48 ? cu : 48;
        int cic = ci < 48 ? ci : 48;
        int c = cuc < cic ? cuc : cic;
        int j = 0;
        for (; j + 4 <= c; j += 4) {
            u0 += g_rs[sidx[j]      * DW + d];
            i0 += g_rs[sidx[48 + j] * DW + d];
            u1 += g_rs[sidx[j + 1]      * DW + d];
            i1 += g_rs[sidx[48 + j + 1] * DW + d];
            u2 += g_rs[sidx[j + 2]      * DW + d];
            i2 += g_rs[sidx[48 + j + 2] * DW + d];
            u3 += g_rs[sidx[j + 3]      * DW + d];
            i3 += g_rs[sidx[48 + j + 3] * DW + d];
        }
        for (int k = j; k < cuc; k++) u0 += g_rs[sidx[k] * DW + d];
        for (int k = j; k < cic; k++) i0 += g_rs[sidx[48 + k] * DW + d];
        for (int k = 48; k < cu; k++) u0 += g_rs[uhi[meta[2] + k] * DW + d];
        for (int k = 48; k < ci; k++) i0 += g_rs[ihi[meta[3] + k] * DW + d];
        float um = ((u0 + u1) + (u2 + u3)) / (float)cu;
        float im = ((i0 + i1) + (i2 + i3)) / (float)ci;
        prod = um * im;
    }
    float s = warp_sum(prod);
    if (lane == 0) red[w] = s;
    __syncthreads();
    if (tid == 0) {
        float t = 0.f;
        #pragma unroll
        for (int k = 0; k < 8; k++) t += red[k];
        float e = t + 3.5f - label[b];
        g_sq[b] = e * e;
        __threadfence();
        rank = atomicAdd(&g_cnt, 1u);
    }
    __syncthreads();

    if (rank == BUSR - 1) {
        __threadfence();
        const float4* h4 = (const float4*)g_hinge;
        float hsum = 0.f;
        #pragma unroll
        for (int r = 0; r < 4; r++) {
            float4 hv = h4[tid + 256 * r];
            hsum += (hv.x + hv.y) + (hv.z + hv.w);
        }
        hsum = warp_sum(hsum);
        if (lane == 0) red[w] = hsum;
        __syncthreads();
        float hs = 0.f;
        if (tid == 0) {
            #pragma unroll
            for (int k = 0; k < 8; k++) hs += red[k];
        }
        __syncthreads();

        float4 qv = ((const float4*)g_sq)[tid];
        float q = (qv.x + qv.y) + (qv.z + qv.w);
        q = warp_sum(q);
        if (lane == 0) red[w] = q;
        __syncthreads();
        if (tid == 0) {
            float rsum = 0.f;
            #pragma unroll
            for (int k = 0; k < 8; k++) rsum += red[k];
            float rating = rsum / (float)BUSR;
            float J = hs / (float)(NREV * NNEG);
            float abae = g_U[0] + J;
            out[0] = rating + abae;
            out[1] = rating;
            out[2] = abae;
            g_cnt = 0u;
        }
    }
}

// ---------------- launch ------------------------------------------------------
extern "C" void kernel_launch(void* const* d_in, const int* in_sizes, int n_in,
                              void* d_out, int out_size) {
    const int*   hist  = (const int*)d_in[0];
    const float* rpos  = (const float*)d_in[1];
    const float* rneg  = (const float*)d_in[2];
    const float* label = (const float*)d_in[5];
    const int*   uhi   = (const int*)d_in[6];
    const int*   usi   = (const int*)d_in[7];
    const int*   ihi   = (const int*)d_in[8];
    const int*   isi   = (const int*)d_in[9];
    const float* wemb  = (const float*)d_in[10];
    const float* Mw    = (const float*)d_in[11];
    const float* Ww    = (const float*)d_in[12];
    const float* Wb    = (const float*)d_in[13];
    const float* Tw    = (const float*)d_in[14];
    float* out = (float*)d_out;
    int F = in_sizes[6];

    const int SMEM_QK   = (DW * DW + 32 * DW) * 4;   // 185600 B
    const int SMEM_MAIN = SM_WORDS * 4;              // 54432 B
    cudaFuncSetAttribute(qk, cudaFuncAttributeMaxDynamicSharedMemorySize, SMEM_QK);
    cudaFuncSetAttribute(mainkern, cudaFuncAttributeMaxDynamicSharedMemorySize, SMEM_MAIN);

    int prep_elems = (AASP * DW > F) ? AASP * DW : F;
    int prep_blocks = (prep_elems + 511) / 512;
    qk<<<QK_BLOCKS + prep_blocks, 512, SMEM_QK>>>(rpos, Mw, Ww, Tw, usi, isi, F);
    mainkern<<<NREV + 1, 256, SMEM_MAIN>>>(hist, wemb, rneg, Wb, Tw);
    segpred<<<BUSR, 256>>>(uhi, ihi, label, out);
}

// round 17
// speedup vs baseline: 1.0948x; 1.0631x over previous
#include <cuda_runtime.h>
#include <cuda_bf16.h>
#include <math.h>

#define NREV 4096
#define LTOK 128
#define DW   200
#define AASP 32
#define NNEG 5
#define BUSR 1024

// ---------------- scratch (device globals) -----------------------------------
__device__ __align__(16) float g_q[NREV * DW];
__device__ __align__(16) float g_rs[NREV * DW];
__device__ __align__(16) float g_hinge[NREV];
__device__ __align__(16) float g_sq[BUSR];
__device__ float g_U[1];
__device__ __align__(16) __nv_bfloat16 g_Wwb[AASP * DW];
__device__ __align__(16) __nv_bfloat16 g_Twb[DW * AASP];
__device__ int g_ubnd[BUSR + 1];
__device__ int g_ibnd[BUSR + 1];
__device__ unsigned int g_cnt;

__device__ __forceinline__ float dot4(float4 a, float4 b) {
    return a.x * b.x + a.y * b.y + a.z * b.z + a.w * b.w;
}
__device__ __forceinline__ float warp_sum(float v) {
    #pragma unroll
    for (int o = 16; o; o >>= 1) v += __shfl_down_sync(0xffffffffu, v, o);
    return v;
}
__device__ __forceinline__ uint2 pack_bf16x4(float4 v) {
    __nv_bfloat162 a = __float22bfloat162_rn(make_float2(v.x, v.y));
    __nv_bfloat162 b = __float22bfloat162_rn(make_float2(v.z, v.w));
    uint2 u;
    u.x = *(unsigned int*)&a;
    u.y = *(unsigned int*)&b;
    return u;
}
__device__ __forceinline__ float2 bf2f(unsigned int u) {
    return __bfloat1622float2(*(__nv_bfloat162*)&u);
}
// ---- f32x2 packed math (sm_103a) ----
__device__ __forceinline__ unsigned long long pk2(float x, float y) {
    unsigned long long r;
    asm("mov.b64 %0, {%1, %2};" : "=l"(r) : "f"(x), "f"(y));
    return r;
}
__device__ __forceinline__ float2 upk2(unsigned long long v) {
    float2 f;
    asm("mov.b64 {%0, %1}, %2;" : "=f"(f.x), "=f"(f.y) : "l"(v));
    return f;
}
__device__ __forceinline__ unsigned long long fma2(unsigned long long a,
                                                   unsigned long long b,
                                                   unsigned long long c) {
    unsigned long long d;
    asm("fma.rn.f32x2 %0, %1, %2, %3;" : "=l"(d) : "l"(a), "l"(b), "l"(c));
    return d;
}

#define QK_BLOCKS (NREV / 32)   // 128 CTAs, 32 reviews each

// ---------------- K1: q = rev_pos @ M_w  (+ fused prep blocks) ----------------
// v6 = v2 skeleton with 8 warps x 8 reviews: halves the m-load crossbar
// redundancy (8 -> 4 review groups) at the same fma2 total. 256 threads.
__global__ __launch_bounds__(256, 1)
void qk(const float* __restrict__ rp, const float* __restrict__ Mw,
        const float* __restrict__ Ww, const float* __restrict__ Tw,
        const int* __restrict__ usi, const int* __restrict__ isi, int F) {
    int tid = threadIdx.x, w = tid >> 5, lane = tid & 31;

    // -------- prep blocks: bf16 weights + segment boundaries --------
    if (blockIdx.x >= QK_BLOCKS) {
        int i = (blockIdx.x - QK_BLOCKS) * 256 + tid;
        if (i < AASP * DW) {
            g_Wwb[i] = __float2bfloat16(Ww[i]);
            g_Twb[i] = __float2bfloat16(Tw[i]);
        }
        if (i < F) {
            int u = usi[i];
            if (i == 0 || usi[i - 1] != u) g_ubnd[u] = i;
            int v = isi[i];
            if (i == 0 || isi[i - 1] != v) g_ibnd[v] = i;
        }
        if (i == 0) { g_ubnd[BUSR] = F; g_ibnd[BUSR] = F; }
        return;
    }

    extern __shared__ float sm[];
    float* Ms  = sm;            // 40000 (fp32, exact)
    float* rps = sm + DW * DW;  // 6400
    {
        const float4* Mw4 = (const float4*)Mw;
        float4* Ms4w = (float4*)Ms;
        for (int i = tid; i < DW * DW / 4; i += 256) Ms4w[i] = __ldg(&Mw4[i]);
        int n0 = blockIdx.x * 32;
        const float4* rp4 = (const float4*)(rp + n0 * DW);
        float4* rps4w = (float4*)rps;
        for (int i = tid; i < 32 * DW / 4; i += 256) rps4w[i] = __ldg(&rp4[i]);
    }
    __syncthreads();

    int wg = w & 3;          // review group: 8 reviews
    int h  = w >> 2;         // output-chunk half
    bool act = (h == 0) || (lane < 18);
    int c = h ? (32 + (lane < 18 ? lane : 0)) : lane;

    const float4* Ms4  = (const float4*)Ms;
    const float4* rps4 = (const float4*)rps;

    unsigned long long acc[8][2];
    #pragma unroll
    for (int j = 0; j < 8; j++) { acc[j][0] = 0ull; acc[j][1] = 0ull; }

    for (int d2b = 0; d2b < 50; d2b++) {
        float4 r4[8];
        #pragma unroll
        for (int j = 0; j < 8; j++) r4[j] = rps4[(wg * 8 + j) * 50 + d2b];  // broadcast
        #pragma unroll
        for (int s = 0; s < 4; s++) {
            float4 m = Ms4[(d2b * 4 + s) * 50 + c];
            unsigned long long m01 = pk2(m.x, m.y), m23 = pk2(m.z, m.w);
            #pragma unroll
            for (int j = 0; j < 8; j++) {
                float r = (s == 0) ? r4[j].x : (s == 1) ? r4[j].y
                        : (s == 2) ? r4[j].z : r4[j].w;
                unsigned long long rr = pk2(r, r);
                acc[j][0] = fma2(rr, m01, acc[j][0]);
                acc[j][1] = fma2(rr, m23, acc[j][1]);
            }
        }
    }

    if (act) {
        int n0 = blockIdx.x * 32;
        float4* gq4 = (float4*)g_q;
        #pragma unroll
        for (int j = 0; j < 8; j++) {
            float2 a0 = upk2(acc[j][0]), a1 = upk2(acc[j][1]);
            float4 o; o.x = a0.x; o.y = a0.y; o.z = a1.x; o.w = a1.y;
            gq4[(n0 + wg * 8 + j) * 50 + c] = o;
        }
    }
}

// ---------------- K2: fused per-review ABAE, bf16 SMEM tile, occ 4 ------------
// Round-12 form (warp-0 softmaxes) — frozen; 4 rewrites of its phases lost.
#define SM_WORDS 13608

__global__ __launch_bounds__(256, 4)
void mainkern(const int* __restrict__ hist, const float* __restrict__ wemb,
              const float* __restrict__ rneg, const float* __restrict__ Wb,
              const float* __restrict__ Tw) {
    extern __shared__ float sm[];
    int n = blockIdx.x;
    int tid = threadIdx.x, w = tid >> 5, lane = tid & 31;

    // -------- extra block: U_loss (exact fp32 Tw) --------
    if (n == NREV) {
        float* Ts  = sm;          // 6400
        float* nrm = sm + 6400;   // 32
        float* red = sm + 6432;   // 8
        for (int i = tid; i < DW * AASP; i += 256) Ts[i] = Tw[i];
        __syncthreads();
        if (tid < AASP) {
            float s = 0.f;
            for (int d = 0; d < DW; d++) { float v = Ts[d * AASP + tid]; s += v * v; }
            nrm[tid] = fmaxf(sqrtf(s), 1e-12f);
        }
        __syncthreads();
        float part = 0.f;
        for (int pr = tid; pr < AASP * AASP; pr += 256) {
            int a = pr >> 5, b = pr & 31;
            float s = 0.f;
            for (int d = 0; d < DW; d++) s += Ts[d * AASP + a] * Ts[d * AASP + b];
            float g = s / (nrm[a] * nrm[b]);
            float diff = g - ((a == b) ? 1.f : 0.f);
            part += diff * diff;
        }
        float v = warp_sum(part);
        if (lane == 0) red[w] = v;
        __syncthreads();
        if (tid == 0) {
            float t = 0.f;
            for (int k = 0; k < 8; k++) t += red[k];
            g_U[0] = t / (float)(AASP * AASP);
        }
        return;
    }

    uint2* eb2  = (uint2*)sm;
    float* qs   = sm + 12800;
    float* ax   = sm + 13000;
    float* zs   = sm + 13128;
    float* p    = sm + 13328;
    float* part = sm + 13360;
    float* tot  = sm + 13464;
    int*   tok  = (int*)(sm + 13480);

    if (tid < LTOK) tok[tid] = hist[n * LTOK + tid];
    if (tid < DW)   qs[tid]  = g_q[n * DW + tid];
    __syncthreads();

    bool hi = (lane < 18);
    const float4* qs4 = (const float4*)qs;
    float4 qv0 = qs4[lane];
    float4 qv1 = hi ? qs4[32 + lane] : make_float4(0, 0, 0, 0);
    const float4* we4 = (const float4*)wemb;

    // -------- single gather + dx (fp32 exact) + bf16 tile store --------
    #pragma unroll
    for (int t0 = 0; t0 < 16; t0 += 4) {
        float4 v0[4], v1[4];
        #pragma unroll
        for (int t = 0; t < 4; t++) {
            int rb = tok[w * 16 + t0 + t] * 50;
            v0[t] = __ldg(&we4[rb + lane]);
            v1[t] = hi ? __ldg(&we4[rb + 32 + lane]) : make_float4(0, 0, 0, 0);
        }
        float a[4];
        #pragma unroll
        for (int t = 0; t < 4; t++) {
            int l = w * 16 + t0 + t;
            eb2[l * 50 + lane] = pack_bf16x4(v0[t]);
            if (hi) eb2[l * 50 + 32 + lane] = pack_bf16x4(v1[t]);
            a[t] = dot4(v0[t], qv0) + dot4(v1[t], qv1);
        }
        #pragma unroll
        for (int t = 0; t < 4; t++) a[t] = warp_sum(a[t]);
        if (lane == 0) {
            #pragma unroll
            for (int t = 0; t < 4; t++) ax[w * 16 + t0 + t] = a[t];
        }
    }
    __syncthreads();

    // -------- softmax over 128 tokens (warp 0) --------
    if (w == 0) {
        float v0 = ax[lane], v1 = ax[lane + 32], v2 = ax[lane + 64], v3 = ax[lane + 96];
        float m = fmaxf(fmaxf(v0, v1), fmaxf(v2, v3));
        #pragma unroll
        for (int o = 16; o; o >>= 1) m = fmaxf(m, __shfl_xor_sync(0xffffffffu, m, o));
        v0 = __expf(v0 - m); v1 = __expf(v1 - m);
        v2 = __expf(v2 - m); v3 = __expf(v3 - m);
        float s = (v0 + v1) + (v2 + v3);
        #pragma unroll
        for (int o = 16; o; o >>= 1) s += __shfl_xor_sync(0xffffffffu, s, o);
        float inv = 1.f / s;
        ax[lane] = v0 * inv; ax[lane + 32] = v1 * inv;
        ax[lane + 64] = v2 * inv; ax[lane + 96] = v3 * inv;
    }
    __syncthreads();

    // -------- z_s from bf16 SMEM tile (reshape trick, flat slices) --------
    {
        const float4* ax4 = (const float4*)ax;
        float4 av = ax4[lane];
        #pragma unroll
        for (int j0 = 0; j0 < 24; j0 += 4) {
            float a[4];
            #pragma unroll
            for (int k = 0; k < 4; k++) {
                int d = w + 8 * (j0 + k);
                uint2 u = eb2[d * 32 + lane];
                float2 f0 = bf2f(u.x), f1 = bf2f(u.y);
                a[k] = f0.x * av.x + f0.y * av.y + f1.x * av.z + f1.y * av.w;
            }
            #pragma unroll
            for (int k = 0; k < 4; k++) a[k] = warp_sum(a[k]);
            if (lane == 0) {
                #pragma unroll
                for (int k = 0; k < 4; k++) zs[w + 8 * (j0 + k)] = a[k];
            }
        }
        {   // leftover d = 192 + w
            int d = 192 + w;
            uint2 u = eb2[d * 32 + lane];
            float2 f0 = bf2f(u.x), f1 = bf2f(u.y);
            float a = warp_sum(f0.x * av.x + f0.y * av.y + f1.x * av.z + f1.y * av.w);
            if (lane == 0) zs[d] = a;
        }
    }
    __syncthreads();

    // -------- prefetch negatives (consumed in final phase) --------
    float ng[NNEG];
    #pragma unroll
    for (int k = 0; k < NNEG; k++)
        ng[k] = (tid < DW) ? __ldg(&rneg[(n * NNEG + k) * DW + tid]) : 0.f;

    // -------- logits = z_s @ W_w^T + W_b (bf16 weights) --------
    {
        const float4* zs4 = (const float4*)zs;
        float4 zv0 = zs4[lane];
        float4 zv1 = hi ? zs4[32 + lane] : make_float4(0, 0, 0, 0);
        const uint2* wb2 = (const uint2*)g_Wwb;
        #pragma unroll
        for (int j = 0; j < 4; j++) {
            int a = w + 8 * j;
            uint2 u0 = __ldg(&wb2[a * 50 + lane]);
            float2 w0 = bf2f(u0.x), w1 = bf2f(u0.y);
            float acc = w0.x * zv0.x + w0.y * zv0.y + w1.x * zv0.z + w1.y * zv0.w;
            if (hi) {
                uint2 u1 = __ldg(&wb2[a * 50 + 32 + lane]);
                float2 w2 = bf2f(u1.x), w3 = bf2f(u1.y);
                acc += w2.x * zv1.x + w2.y * zv1.y + w3.x * zv1.z + w3.y * zv1.w;
            }
            acc = warp_sum(acc);
            if (lane == 0) p[a] = acc + Wb[a];
        }
    }
    __syncthreads();

    // -------- softmax over A=32 (warp 0) --------
    if (w == 0) {
        float v = p[lane];
        float m = v;
        #pragma unroll
        for (int o = 16; o; o >>= 1) m = fmaxf(m, __shfl_xor_sync(0xffffffffu, m, o));
        float ex = __expf(v - m);
        float s = ex;
        #pragma unroll
        for (int o = 16; o; o >>= 1) s += __shfl_xor_sync(0xffffffffu, s, o);
        p[lane] = ex / s;
    }
    __syncthreads();

    // -------- r_s = p @ T_w^T (bf16 Tw row) ; 13 fused dots --------
    float rsv = 0.f, zsv = 0.f;
    if (tid < DW) {
        const uint4* tb4 = (const uint4*)(g_Twb + tid * AASP);
        float acc = 0.f;
        #pragma unroll
        for (int j = 0; j < 4; j++) {
            uint4 t = __ldg(&tb4[j]);
            float2 a0 = bf2f(t.x), a1 = bf2f(t.y), a2 = bf2f(t.z), a3 = bf2f(t.w);
            acc += a0.x * p[j * 8 + 0] + a0.y * p[j * 8 + 1]
                 + a1.x * p[j * 8 + 2] + a1.y * p[j * 8 + 3]
                 + a2.x * p[j * 8 + 4] + a2.y * p[j * 8 + 5]
                 + a3.x * p[j * 8 + 6] + a3.y * p[j * 8 + 7];
        }
        g_rs[n * DW + tid] = acc;
        rsv = acc;
        zsv = zs[tid];
    }

    float v[13];
    v[0] = zsv * zsv; v[1] = rsv * rsv; v[2] = zsv * rsv;
    #pragma unroll
    for (int k = 0; k < NNEG; k++) { v[3 + k] = ng[k] * ng[k]; v[8 + k] = ng[k] * rsv; }
    #pragma unroll
    for (int x = 0; x < 13; x++) v[x] = warp_sum(v[x]);
    if (lane == 0) {
        #pragma unroll
        for (int x = 0; x < 13; x++) part[w * 13 + x] = v[x];
    }
    __syncthreads();
    if (w == 0 && lane < 13) {
        float s = 0.f;
        #pragma unroll
        for (int k = 0; k < 8; k++) s += part[k * 13 + lane];
        tot[lane] = s;
    }
    __syncthreads();
    if (tid == 0) {
        float nz = fmaxf(sqrtf(tot[0]), 1e-12f);
        float nr = fmaxf(sqrtf(tot[1]), 1e-12f);
        float c1 = tot[2] / (nz * nr);
        float h = 0.f;
        #pragma unroll
        for (int k = 0; k < NNEG; k++) {
            float c2 = tot[8 + k] / (fmaxf(sqrtf(tot[3 + k]), 1e-12f) * nr);
            h += fmaxf(0.f, c2 - c1);
        }
        g_hinge[n] = h;
    }
}

// ---------------- K3: segment means + prediction + final reduce ---------------
__global__ __launch_bounds__(256, 8)
void segpred(const int* __restrict__ uhi, const int* __restrict__ ihi,
             const float* __restrict__ label, float* __restrict__ out) {
    int b = blockIdx.x;
    int tid = threadIdx.x, w = tid >> 5, lane = tid & 31;
    __shared__ int sidx[96];
    __shared__ int meta[4];
    __shared__ float red[8];
    __shared__ unsigned int rank;

    if (w < 2) {
        const int* bnd = w ? g_ibnd : g_ubnd;
        const int* idx = w ? ihi : uhi;
        int lo = bnd[b], hi2 = bnd[b + 1];
        int cnt = hi2 - lo;
        if (lane == 0) { meta[w] = cnt; meta[2 + w] = lo; }
        for (int j = lane; j < cnt && j < 48; j += 32)
            sidx[w * 48 + j] = idx[lo + j];
    }
    __syncthreads();

    int cu = meta[0], ci = meta[1];
    float prod = 0.f;
    int d = tid;
    if (d < DW) {
        float u0 = 0.f, u1 = 0.f, u2 = 0.f, u3 = 0.f;
        float i0 = 0.f, i1 = 0.f, i2 = 0.f, i3 = 0.f;
        int cuc = cu < 48 ? cu : 48;
        int cic = ci < 48 ? ci : 48;
        int c = cuc < cic ? cuc : cic;
        int j = 0;
        for (; j + 4 <= c; j += 4) {
            u0 += g_rs[sidx[j]      * DW + d];
            i0 += g_rs[sidx[48 + j] * DW + d];
            u1 += g_rs[sidx[j + 1]      * DW + d];
            i1 += g_rs[sidx[48 + j + 1] * DW + d];
            u2 += g_rs[sidx[j + 2]      * DW + d];
            i2 += g_rs[sidx[48 + j + 2] * DW + d];
            u3 += g_rs[sidx[j + 3]      * DW + d];
            i3 += g_rs[sidx[48 + j + 3] * DW + d];
        }
        for (int k = j; k < cuc; k++) u0 += g_rs[sidx[k] * DW + d];
        for (int k = j; k < cic; k++) i0 += g_rs[sidx[48 + k] * DW + d];
        for (int k = 48; k < cu; k++) u0 += g_rs[uhi[meta[2] + k] * DW + d];
        for (int k = 48; k < ci; k++) i0 += g_rs[ihi[meta[3] + k] * DW + d];
        float um = ((u0 + u1) + (u2 + u3)) / (float)cu;
        float im = ((i0 + i1) + (i2 + i3)) / (float)ci;
        prod = um * im;
    }
    float s = warp_sum(prod);
    if (lane == 0) red[w] = s;
    __syncthreads();
    if (tid == 0) {
        float t = 0.f;
        #pragma unroll
        for (int k = 0; k < 8; k++) t += red[k];
        float e = t + 3.5f - label[b];
        g_sq[b] = e * e;
        __threadfence();
        rank = atomicAdd(&g_cnt, 1u);
    }
    __syncthreads();

    if (rank == BUSR - 1) {
        __threadfence();
        const float4* h4 = (const float4*)g_hinge;
        float hsum = 0.f;
        #pragma unroll
        for (int r = 0; r < 4; r++) {
            float4 hv = h4[tid + 256 * r];
            hsum += (hv.x + hv.y) + (hv.z + hv.w);
        }
        hsum = warp_sum(hsum);
        if (lane == 0) red[w] = hsum;
        __syncthreads();
        float hs = 0.f;
        if (tid == 0) {
            #pragma unroll
            for (int k = 0; k < 8; k++) hs += red[k];
        }
        __syncthreads();

        float4 qv = ((const float4*)g_sq)[tid];
        float q = (qv.x + qv.y) + (qv.z + qv.w);
        q = warp_sum(q);
        if (lane == 0) red[w] = q;
        __syncthreads();
        if (tid == 0) {
            float rsum = 0.f;
            #pragma unroll
            for (int k = 0; k < 8; k++) rsum += red[k];
            float rating = rsum / (float)BUSR;
            float J = hs / (float)(NREV * NNEG);
            float abae = g_U[0] + J;
            out[0] = rating + abae;
            out[1] = rating;
            out[2] = abae;
            g_cnt = 0u;
        }
    }
}

// ---------------- launch ------------------------------------------------------
extern "C" void kernel_launch(void* const* d_in, const int* in_sizes, int n_in,
                              void* d_out, int out_size) {
    const int*   hist  = (const int*)d_in[0];
    const float* rpos  = (const float*)d_in[1];
    const float* rneg  = (const float*)d_in[2];
    const float* label = (const float*)d_in[5];
    const int*   uhi   = (const int*)d_in[6];
    const int*   usi   = (const int*)d_in[7];
    const int*   ihi   = (const int*)d_in[8];
    const int*   isi   = (const int*)d_in[9];
    const float* wemb  = (const float*)d_in[10];
    const float* Mw    = (const float*)d_in[11];
    const float* Ww    = (const float*)d_in[12];
    const float* Wb    = (const float*)d_in[13];
    const float* Tw    = (const float*)d_in[14];
    float* out = (float*)d_out;
    int F = in_sizes[6];

    const int SMEM_QK   = (DW * DW + 32 * DW) * 4;   // 185600 B
    const int SMEM_MAIN = SM_WORDS * 4;              // 54432 B
    cudaFuncSetAttribute(qk, cudaFuncAttributeMaxDynamicSharedMemorySize, SMEM_QK);
    cudaFuncSetAttribute(mainkern, cudaFuncAttributeMaxDynamicSharedMemorySize, SMEM_MAIN);

    int prep_elems = (AASP * DW > F) ? AASP * DW : F;
    int prep_blocks = (prep_elems + 255) / 256;
    qk<<<QK_BLOCKS + prep_blocks, 256, SMEM_QK>>>(rpos, Mw, Ww, Tw, usi, isi, F);
    mainkern<<<NREV + 1, 256, SMEM_MAIN>>>(hist, wemb, rneg, Wb, Tw);
    segpred<<<BUSR, 256>>>(uhi, ihi, label, out);
}